// round 1
// baseline (speedup 1.0000x reference)
#include <cuda_runtime.h>

#define D    64
#define KC   512
#define TPB  256
#define RPT  2
#define LDW  68   // padded SMEM row stride (floats): 16B-aligned, breaks 32-way conflicts

__device__ double g_loss_sum;

__global__ void vq_init_kernel() { g_loss_sum = 0.0; }

__global__ void __launch_bounds__(TPB, 1)
vq_main_kernel(const float* __restrict__ x, const float* __restrict__ emb,
               float* __restrict__ out_q, float* __restrict__ out_idx, int n_rows)
{
    extern __shared__ float smem[];
    float* sw = smem;             // [KC][LDW] transposed codebook
    float* hw = smem + KC * LDW;  // [KC] 0.5*||w_k||^2

    // Load + transpose embeddings (global layout [D][K]) — coalesced global reads.
    for (int i = threadIdx.x; i < D * KC; i += TPB) {
        int d = i >> 9;          // i / 512
        int k = i & (KC - 1);    // i % 512
        sw[k * LDW + d] = emb[i];
    }
    __syncthreads();
    for (int k = threadIdx.x; k < KC; k += TPB) {
        const float* w = sw + k * LDW;
        float s = 0.f;
        #pragma unroll
        for (int d = 0; d < D; d++) s += w[d] * w[d];
        hw[k] = 0.5f * s;
    }
    __syncthreads();

    const int r0 = blockIdx.x * (TPB * RPT) + threadIdx.x;
    const int r1 = r0 + TPB;
    const bool v0 = r0 < n_rows;
    const bool v1 = r1 < n_rows;

    float x0[D], x1[D];
    if (v0) {
        const float4* p = (const float4*)(x + (size_t)r0 * D);
        #pragma unroll
        for (int j = 0; j < D / 4; j++) {
            float4 t = p[j];
            x0[4*j] = t.x; x0[4*j+1] = t.y; x0[4*j+2] = t.z; x0[4*j+3] = t.w;
        }
    } else {
        #pragma unroll
        for (int j = 0; j < D; j++) x0[j] = 0.f;
    }
    if (v1) {
        const float4* p = (const float4*)(x + (size_t)r1 * D);
        #pragma unroll
        for (int j = 0; j < D / 4; j++) {
            float4 t = p[j];
            x1[4*j] = t.x; x1[4*j+1] = t.y; x1[4*j+2] = t.z; x1[4*j+3] = t.w;
        }
    } else {
        #pragma unroll
        for (int j = 0; j < D; j++) x1[j] = 0.f;
    }

    float best0 = -3.402823466e38f, best1 = -3.402823466e38f;
    int   b0 = 0, b1 = 0;

    #pragma unroll 1
    for (int k = 0; k < KC; k++) {
        const float4* wr = (const float4*)(sw + k * LDW);
        float a0 = 0.f, c0 = 0.f, a1 = 0.f, c1 = 0.f;  // 2 partial chains per row
        #pragma unroll
        for (int j = 0; j < 16; j += 2) {
            float4 w  = wr[j];
            float4 w2 = wr[j + 1];
            a0 = fmaf(x0[4*j+3], w.w,  fmaf(x0[4*j+2], w.z,  fmaf(x0[4*j+1], w.y,  fmaf(x0[4*j+0], w.x,  a0))));
            c0 = fmaf(x0[4*j+7], w2.w, fmaf(x0[4*j+6], w2.z, fmaf(x0[4*j+5], w2.y, fmaf(x0[4*j+4], w2.x, c0))));
            a1 = fmaf(x1[4*j+3], w.w,  fmaf(x1[4*j+2], w.z,  fmaf(x1[4*j+1], w.y,  fmaf(x1[4*j+0], w.x,  a1))));
            c1 = fmaf(x1[4*j+7], w2.w, fmaf(x1[4*j+6], w2.z, fmaf(x1[4*j+5], w2.y, fmaf(x1[4*j+4], w2.x, c1))));
        }
        float hwk = hw[k];
        float s0 = (a0 + c0) - hwk;
        float s1 = (a1 + c1) - hwk;
        if (s0 > best0) { best0 = s0; b0 = k; }   // strict > keeps first index (argmin semantics)
        if (s1 > best1) { best1 = s1; b1 = k; }
    }

    // Epilogue: gather winning code, write quantized + index, accumulate loss.
    double lsum = 0.0;
    if (v0) {
        const float* w = sw + b0 * LDW;
        float4* q = (float4*)(out_q + (size_t)r0 * D);
        #pragma unroll
        for (int j = 0; j < 16; j++) {
            float4 t;
            t.x = w[4*j]; t.y = w[4*j+1]; t.z = w[4*j+2]; t.w = w[4*j+3];
            q[j] = t;
            float d0 = t.x - x0[4*j],   d1 = t.y - x0[4*j+1];
            float d2 = t.z - x0[4*j+2], d3 = t.w - x0[4*j+3];
            lsum += (double)(d0*d0 + d1*d1 + d2*d2 + d3*d3);
        }
        out_idx[r0] = (float)b0;
    }
    if (v1) {
        const float* w = sw + b1 * LDW;
        float4* q = (float4*)(out_q + (size_t)r1 * D);
        #pragma unroll
        for (int j = 0; j < 16; j++) {
            float4 t;
            t.x = w[4*j]; t.y = w[4*j+1]; t.z = w[4*j+2]; t.w = w[4*j+3];
            q[j] = t;
            float d0 = t.x - x1[4*j],   d1 = t.y - x1[4*j+1];
            float d2 = t.z - x1[4*j+2], d3 = t.w - x1[4*j+3];
            lsum += (double)(d0*d0 + d1*d1 + d2*d2 + d3*d3);
        }
        out_idx[r1] = (float)b1;
    }

    // Block reduction of loss partials -> one atomic per block.
    unsigned mask = 0xffffffffu;
    #pragma unroll
    for (int off = 16; off; off >>= 1) lsum += __shfl_down_sync(mask, lsum, off);
    __shared__ double red[TPB / 32];
    int wid  = threadIdx.x >> 5;
    int lane = threadIdx.x & 31;
    if (lane == 0) red[wid] = lsum;
    __syncthreads();
    if (wid == 0) {
        double v = (lane < TPB / 32) ? red[lane] : 0.0;
        #pragma unroll
        for (int off = 4; off; off >>= 1) v += __shfl_down_sync(mask, v, off);
        if (lane == 0) atomicAdd(&g_loss_sum, v);
    }
}

__global__ void vq_fin_kernel(float* __restrict__ out_loss, double inv_count)
{
    // loss = mean(sq) + 0.25*mean(sq) = 1.25 * mean(sq)  (stop_gradient is identity on values)
    *out_loss = (float)(1.25 * g_loss_sum * inv_count);
}

extern "C" void kernel_launch(void* const* d_in, const int* in_sizes, int n_in,
                              void* d_out, int out_size)
{
    const float* x   = (const float*)d_in[0];   // [N, 64] flattened inputs
    const float* emb = (const float*)d_in[1];   // [64, 512]

    const int n_rows = in_sizes[0] / D;         // 65536
    float* out      = (float*)d_out;
    float* out_q    = out;                               // N*D quantized_st
    float* out_idx  = out + (size_t)n_rows * D;          // N indices (as f32)
    float* out_loss = out_idx + n_rows;                  // 1 scalar loss

    size_t smem_bytes = (size_t)(KC * LDW + KC) * sizeof(float);
    cudaFuncSetAttribute(vq_main_kernel,
                         cudaFuncAttributeMaxDynamicSharedMemorySize,
                         (int)smem_bytes);

    int grid = (n_rows + TPB * RPT - 1) / (TPB * RPT);   // 128 blocks

    vq_init_kernel<<<1, 1>>>();
    vq_main_kernel<<<grid, TPB, smem_bytes>>>(x, emb, out_q, out_idx, n_rows);
    vq_fin_kernel<<<1, 1>>>(out_loss, 1.0 / ((double)n_rows * (double)D));
}